// round 15
// baseline (speedup 1.0000x reference)
#include <cuda_runtime.h>
#include <cstddef>
#include <cstdint>

// Sizes: B=64, S=1024, E=256 (== proj dim), H=1024, G=4*H=4096
#define NB 64
#define NS 1024
#define NE 256
#define NH 1024
#define NG 4096
#define RBLK 128

// phase-2 smem layout (float offsets)
#define WHH0_OFF 0            // [32][260] = 8320
#define WHH1_OFF 8320
#define WHR0_OFF 16640        // [8][1028] = 8224
#define WHR1_OFF 24864
#define HBUF_OFF 33088        // h [64][260]=16640  (aliases proj a [16][1028])
#define GS_OFF 49728          // max(32*65=2080, 128*17=2176) -> 2304
#define POOL_FLOATS 52032     // 208128 bytes
// phase-1 aliases (phase-separated by grid barrier)
#define P1_WS 0               // 8*2304 = 18432
#define P1_AB 18432           // 4*2304 = 9216
#define P1_GS 27648           // 64*65  = 4160

// ---------------- device scratch (static: no runtime allocation) ------------
__device__ float g_xg[2][(size_t)NS * NB * NG];  // 2 GiB  xg [dir][s][b][g]
__device__ float g_xq[(size_t)NB * NS * NE];     // 64 MB  x rounded to tf32
__device__ float g_hq[2][2][NB * NE];            // [parity][dir] rounded h
__device__ float g_a[2][NB * NH];                // [dir][b*1024+j] rounded
__device__ unsigned g_ctr[4];
__device__ unsigned g_flagA[2][RBLK * 16];       // a(t) published (value t+1)
__device__ unsigned g_flagH[2][RBLK * 16];       // h(t+1) published (value t+1)

__device__ __forceinline__ float sigf(float x) { return 1.0f / (1.0f + __expf(-x)); }
__device__ __forceinline__ float tanh_f(float x) {
    float e = __expf(2.0f * x);
    return 1.0f - 2.0f / (e + 1.0f);
}

__device__ __forceinline__ uint4 cvt4(float4 v) {
    uint4 u;
    asm("cvt.rna.tf32.f32 %0, %1;" : "=r"(u.x) : "f"(v.x));
    asm("cvt.rna.tf32.f32 %0, %1;" : "=r"(u.y) : "f"(v.y));
    asm("cvt.rna.tf32.f32 %0, %1;" : "=r"(u.z) : "f"(v.z));
    asm("cvt.rna.tf32.f32 %0, %1;" : "=r"(u.w) : "f"(v.w));
    return u;
}
__device__ __forceinline__ float cvt1(float v) {
    uint32_t u;
    asm("cvt.rna.tf32.f32 %0, %1;" : "=r"(u) : "f"(v));
    return __uint_as_float(u);
}

__device__ __forceinline__ void mma_tf32(float* acc,
                                         uint32_t a0, uint32_t a1, uint32_t a2, uint32_t a3,
                                         uint32_t b0, uint32_t b1) {
    asm volatile(
        "mma.sync.aligned.m16n8k8.row.col.f32.tf32.tf32.f32 "
        "{%0,%1,%2,%3}, {%4,%5,%6,%7}, {%8,%9}, {%0,%1,%2,%3};"
        : "+f"(acc[0]), "+f"(acc[1]), "+f"(acc[2]), "+f"(acc[3])
        : "r"(a0), "r"(a1), "r"(a2), "r"(a3), "r"(b0), "r"(b1));
}

// phase-1 helper (stride-36 tiles)
template <int NTS>
__device__ __forceinline__ void warp_mma_chunk(const uint32_t* __restrict__ Au,
                                               const uint32_t* __restrict__ Bu,
                                               int mg, int ngb, int l,
                                               float acc[][4]) {
#pragma unroll
    for (int ks = 0; ks < 4; ks++) {
        int k0 = ks * 8 + (l & 3);
        int ra = (mg + (l >> 2)) * 36 + k0;
        uint32_t a0 = Au[ra];
        uint32_t a1 = Au[ra + 8 * 36];
        uint32_t a2 = Au[ra + 4];
        uint32_t a3 = Au[ra + 8 * 36 + 4];
#pragma unroll
        for (int nt = 0; nt < NTS; nt++) {
            int rb = (ngb + nt * 8 + (l >> 2)) * 36 + k0;
            mma_tf32(acc[nt], a0, a1, a2, a3, Bu[rb], Bu[rb + 4]);
        }
    }
}

__device__ __forceinline__ void fillA_raw(float* __restrict__ dst,
                                          const float* __restrict__ src,
                                          int k0, size_t rowstride, int t2) {
#pragma unroll
    for (int i = 0; i < 2; i++) {
        int f = t2 + i * 256;
        int r = f >> 3;
        int kq = (f & 7) << 2;
        float4 v = __ldcg((const float4*)&src[(size_t)r * rowstride + k0 + kq]);
        *(float4*)&dst[r * 36 + kq] = v;
    }
}

__device__ __forceinline__ unsigned ldacq(const unsigned* p) {
    unsigned v;
    asm volatile("ld.global.acquire.gpu.u32 %0, [%1];" : "=r"(v) : "l"(p) : "memory");
    return v;
}
__device__ __forceinline__ void strel(unsigned* p, unsigned v) {
    asm volatile("st.global.release.gpu.u32 [%0], %1;" :: "l"(p), "r"(v) : "memory");
}

__device__ __forceinline__ void gbar(unsigned* c, unsigned target) {
    __syncthreads();
    if (threadIdx.x == 0) {
        __threadfence();
        atomicAdd(c, 1u);
        unsigned v;
        do { v = ldacq(c); } while (v < target);
    }
    __syncthreads();
}

// --------------------------- init ------------------------------------------
__global__ void init_kernel() {
    int i = blockIdx.x * blockDim.x + threadIdx.x;   // 128 x 512 = 65536
    if (i < 4) g_ctr[i] = 0u;
    if (i < 2 * RBLK * 16) { g_flagA[0][i & (RBLK * 16 - 1)] = 0u; }
    if (i >= 2 * RBLK * 16 && i < 4 * RBLK * 16) g_flagA[1][i - 2 * RBLK * 16] = 0u;
    if (i < RBLK * 16) { g_flagH[0][i] = 0u; g_flagH[1][i] = 0u; }
    if (i < 2 * 2 * NB * NE) (&g_hq[0][0][0])[i] = 0.0f;
}

// --------------------------- the whole network ------------------------------
__global__ __launch_bounds__(512, 1) void lstm_kernel(
    const float* __restrict__ x,
    const float* __restrict__ Wihf, const float* __restrict__ Whhf,
    const float* __restrict__ bihf, const float* __restrict__ bhhf,
    const float* __restrict__ Whrf,
    const float* __restrict__ Wihb, const float* __restrict__ Whhb,
    const float* __restrict__ bihb, const float* __restrict__ bhhb,
    const float* __restrict__ Whrb,
    float* __restrict__ out)
{
    extern __shared__ __align__(16) float pool[];

    const int bid = blockIdx.x;
    const int tid = threadIdx.x;
    const int l   = tid & 31;
    const int wid = tid >> 5;          // warp 0..15

    // ---------------- phase 0: round x into g_xq ----------------------------
    {
        const size_t n4 = (size_t)NB * NS * NE / 4;
        for (size_t i4 = (size_t)bid * 512 + tid; i4 < n4; i4 += (size_t)RBLK * 512) {
            float4 v = ((const float4*)x)[i4];
            *(uint4*)&((float4*)g_xq)[i4] = cvt4(v);
        }
    }
    gbar(&g_ctr[0], (unsigned)RBLK);

    // ---------------- phase 1: xg = x @ W_ih^T + (b_ih + b_hh)  (R11) -------
    {
        const int dir1 = bid >> 6;
        const int u1   = bid & 63;
        const int kg = tid >> 8;
        const int t2 = tid & 255;
        const int wi = t2 >> 5;
        const int mg1 = (wi & 3) << 4;
        const int ngb = (wi >> 2) << 5;
        const int n0 = u1 << 6;
        const float* __restrict__ W  = dir1 ? Wihb : Wihf;
        const float* __restrict__ bi = dir1 ? bihb : bihf;
        const float* __restrict__ bh = dir1 ? bhhb : bhhf;
        float* __restrict__ xo = g_xg[dir1];
        uint32_t* WS = (uint32_t*)(pool + P1_WS);
        float* Ab = pool + P1_AB + kg * 2 * 2304;
        float* gs1 = pool + P1_GS;

#pragma unroll
        for (int ci = 0; ci < 8; ci++) {
            int r = tid >> 3;
            int kq = (tid & 7) << 2;
            float4 wv = *(const float4*)&W[(size_t)(n0 + r) * NE + ci * 32 + kq];
            *(uint4*)&WS[ci * 2304 + r * 36 + kq] = cvt4(wv);
        }
        float bias0[4], bias1[4];
#pragma unroll
        for (int nt = 0; nt < 4; nt++) {
            int c = ngb + nt * 8 + ((l & 3) << 1);
            bias0[nt] = bi[n0 + c] + bh[n0 + c];
            bias1[nt] = bi[n0 + c + 1] + bh[n0 + c + 1];
        }
        __syncthreads();

        for (int s = 0; s < NS; s++) {
            const float* xsrc = g_xq + (size_t)s * NE;
            float acc[4][4];
#pragma unroll
            for (int a = 0; a < 4; a++)
#pragma unroll
                for (int q = 0; q < 4; q++) acc[a][q] = 0.0f;

            fillA_raw(Ab, xsrc, kg * 128, (size_t)NS * NE, t2);
            __syncthreads();
#pragma unroll
            for (int rr = 0; rr < 4; rr++) {
                if (rr < 3)
                    fillA_raw(Ab + ((rr + 1) & 1) * 2304, xsrc,
                              kg * 128 + (rr + 1) * 32, (size_t)NS * NE, t2);
                warp_mma_chunk<4>((uint32_t*)(Ab + (rr & 1) * 2304),
                                  WS + (kg * 4 + rr) * 2304, mg1, ngb, l, acc);
                __syncthreads();
            }
            if (kg == 1) {
#pragma unroll
                for (int nt = 0; nt < 4; nt++) {
                    int c = ngb + nt * 8 + ((l & 3) << 1);
                    int r = mg1 + (l >> 2);
                    gs1[c * 65 + r]           = acc[nt][0];
                    gs1[(c + 1) * 65 + r]     = acc[nt][1];
                    gs1[c * 65 + r + 8]       = acc[nt][2];
                    gs1[(c + 1) * 65 + r + 8] = acc[nt][3];
                }
            }
            __syncthreads();
            if (kg == 0) {
#pragma unroll
                for (int nt = 0; nt < 4; nt++) {
                    int c = ngb + nt * 8 + ((l & 3) << 1);
                    int r = mg1 + (l >> 2);
                    float2 o0, o1;
                    o0.x = acc[nt][0] + gs1[c * 65 + r] + bias0[nt];
                    o0.y = acc[nt][1] + gs1[(c + 1) * 65 + r] + bias1[nt];
                    o1.x = acc[nt][2] + gs1[c * 65 + r + 8] + bias0[nt];
                    o1.y = acc[nt][3] + gs1[(c + 1) * 65 + r + 8] + bias1[nt];
                    __stcs((float2*)&xo[((size_t)s * NB + r) * NG + n0 + c], o0);
                    __stcs((float2*)&xo[((size_t)s * NB + r + 8) * NG + n0 + c], o1);
                }
            }
            __syncthreads();
        }
    }
    gbar(&g_ctr[0], 2u * RBLK);

    // ---------------- phase 2: dual-direction interleaved recurrence --------
    const int j0 = bid << 3;               // 8 hidden units (both dirs)
    const int b0 = (bid >> 5) << 4;        // proj: 16-batch tile
    const int p0 = (bid & 31) << 3;        // proj: 8-col tile
    const int mgrp = (wid & 3) << 4;       // gates m-group
    const int ngrp = ((wid >> 2) & 1) << 4;// gates n-group (16 cols)
    const int kgrp = wid >> 3;             // gates k-half (128)

    float* WhhS[2] = {pool + WHH0_OFF, pool + WHH1_OFF};   // [32][260]
    float* WhrS[2] = {pool + WHR0_OFF, pool + WHR1_OFF};   // [8][1028]
    float* hBuf = pool + HBUF_OFF;        // [64][260]; proj a aliases [16][1028]
    float* gs = pool + GS_OFF;

    // ---- weights into smem ONCE (pre-converted tf32) -----------------------
#pragma unroll
    for (int d = 0; d < 2; d++) {
        const float* __restrict__ Whh = d ? Whhb : Whhf;
        const float* __restrict__ Whr = d ? Whrb : Whrf;
#pragma unroll
        for (int i = 0; i < 4; i++) {
            int f = tid + i * 512;             // 0..2047: 32 rows x 64 f4
            int c = f >> 6;
            int kq = (f & 63) << 2;
            int g = ((c >> 3) << 10) + j0 + (c & 7);
            float4 wv = *(const float4*)&Whh[(size_t)g * NE + kq];
            *(uint4*)&WhhS[d][c * 260 + kq] = cvt4(wv);
        }
#pragma unroll
        for (int i = 0; i < 4; i++) {
            int f = tid + i * 512;             // 0..2047: 8 cols x 256 f4
            int c = f >> 8;
            int kq = (f & 255) << 2;
            float4 wv = *(const float4*)&Whr[(size_t)(p0 + c) * NH + kq];
            *(uint4*)&WhrS[d][c * 1028 + kq] = cvt4(wv);
        }
    }
    __syncthreads();

    float creg[2] = {0.0f, 0.0f};          // cell state: 1 (unit,b) pair per dir
    const int jl = tid & 7, bb = tid >> 3; // cell mapping: 8 units x 64 batches

    for (int t = 0; t < NS; t++) {
        const int par = t & 1;
        const int sd[2] = {t, NS - 1 - t};

        // xg prefetch, both dirs (overlaps the first wait)
        float xgv[2][4];
#pragma unroll
        for (int d = 0; d < 2; d++) {
            const float* p = &g_xg[d][((size_t)sd[d] * NB + bb) * NG + j0 + jl];
            xgv[d][0] = __ldcs(p);
            xgv[d][1] = __ldcs(p + 1024);
            xgv[d][2] = __ldcs(p + 2048);
            xgv[d][3] = __ldcs(p + 3072);
        }

        // ================= gates + cell, dir 0 then dir 1 ==================
#pragma unroll
        for (int d = 0; d < 2; d++) {
            if (t > 0 && tid < RBLK) {
                while (ldacq(&g_flagH[d][tid * 16]) < (unsigned)t) { }
            }
            __syncthreads();

            // fill h(t) -> hBuf [64][260]
            const float* __restrict__ h = g_hq[par][d];
#pragma unroll
            for (int i = 0; i < 8; i++) {
                int f = tid + i * 512;
                int r = f >> 6, q = f & 63;
                float4 v = __ldcg((const float4*)&h[r * NE + (q << 2)]);
                *(float4*)&hBuf[r * 260 + (q << 2)] = v;
            }
            __syncthreads();

            // m16 x n16 x k128 per warp; 4m x 2n x 2k
            float acc[2][4];
#pragma unroll
            for (int a = 0; a < 2; a++)
#pragma unroll
                for (int q = 0; q < 4; q++) acc[a][q] = 0.0f;

            const uint32_t* hU = (const uint32_t*)hBuf;
            const uint32_t* bU = (const uint32_t*)WhhS[d];
#pragma unroll
            for (int ks = 0; ks < 16; ks++) {
                int k0 = kgrp * 128 + ks * 8 + (l & 3);
                int ra = (mgrp + (l >> 2)) * 260 + k0;
                uint32_t a0 = hU[ra];
                uint32_t a1 = hU[ra + 8 * 260];
                uint32_t a2 = hU[ra + 4];
                uint32_t a3 = hU[ra + 8 * 260 + 4];
#pragma unroll
                for (int nt = 0; nt < 2; nt++) {
                    int rb = (ngrp + nt * 8 + (l >> 2)) * 260 + k0;
                    mma_tf32(acc[nt], a0, a1, a2, a3, bU[rb], bU[rb + 4]);
                }
            }
            // 2-way k merge into gs [c*65 + r]
            if (kgrp == 1) {
#pragma unroll
                for (int nt = 0; nt < 2; nt++) {
                    int c = ngrp + nt * 8 + ((l & 3) << 1);
                    int r = mgrp + (l >> 2);
                    gs[c * 65 + r]           = acc[nt][0];
                    gs[(c + 1) * 65 + r]     = acc[nt][1];
                    gs[c * 65 + r + 8]       = acc[nt][2];
                    gs[(c + 1) * 65 + r + 8] = acc[nt][3];
                }
            }
            __syncthreads();
            if (kgrp == 0) {
#pragma unroll
                for (int nt = 0; nt < 2; nt++) {
                    int c = ngrp + nt * 8 + ((l & 3) << 1);
                    int r = mgrp + (l >> 2);
                    gs[c * 65 + r]           += acc[nt][0];
                    gs[(c + 1) * 65 + r]     += acc[nt][1];
                    gs[c * 65 + r + 8]       += acc[nt][2];
                    gs[(c + 1) * 65 + r + 8] += acc[nt][3];
                }
            }
            __syncthreads();

            // cell update: col layout c = tt*8 + jl
            {
                float gi = gs[( 0 + jl) * 65 + bb] + xgv[d][0];
                float gf = gs[( 8 + jl) * 65 + bb] + xgv[d][1];
                float gg = gs[(16 + jl) * 65 + bb] + xgv[d][2];
                float go = gs[(24 + jl) * 65 + bb] + xgv[d][3];
                float cn = sigf(gf) * creg[d] + sigf(gi) * tanh_f(gg);
                creg[d] = cn;
                g_a[d][bb * NH + j0 + jl] = cvt1(sigf(go) * tanh_f(cn));
            }
            __syncthreads();
            if (tid == 0) {
                __threadfence();
                strel(&g_flagA[d][bid * 16], (unsigned)(t + 1));
            }
        }

        // ================= projection, dir 0 then dir 1 ====================
#pragma unroll
        for (int d = 0; d < 2; d++) {
            if (tid < RBLK) {
                while (ldacq(&g_flagA[d][tid * 16]) < (unsigned)(t + 1)) { }
            }
            __syncthreads();

            // fill a rows b0..b0+15 -> aBuf [16][1028] (aliases hBuf)
#pragma unroll
            for (int i = 0; i < 8; i++) {
                int f = tid + i * 512;
                int r = f >> 8;
                int kq = (f & 255) << 2;
                float4 v = __ldcg((const float4*)&g_a[d][(size_t)(b0 + r) * NH + kq]);
                *(float4*)&hBuf[r * 1028 + kq] = v;
            }
            __syncthreads();

            // m16 x n8, K=1024 split 16 ways across warps
            const uint32_t* aU = (const uint32_t*)hBuf;
            const uint32_t* wU = (const uint32_t*)WhrS[d];
            float pacc[4];
            pacc[0] = pacc[1] = pacc[2] = pacc[3] = 0.0f;
            const int kw = wid * 64;
#pragma unroll
            for (int ks = 0; ks < 8; ks++) {
                int k0 = kw + ks * 8 + (l & 3);
                int ra = (l >> 2) * 1028 + k0;
                uint32_t a0 = aU[ra];
                uint32_t a1 = aU[ra + 8 * 1028];
                uint32_t a2 = aU[ra + 4];
                uint32_t a3 = aU[ra + 8 * 1028 + 4];
                int rb = (l >> 2) * 1028 + k0;
                mma_tf32(pacc, a0, a1, a2, a3, wU[rb], wU[rb + 4]);
            }
            // partials: gs[(r*8 + c)*17 + wid]
            {
                int c0 = (l & 3) << 1;
                int r0 = l >> 2;
                gs[(r0 * 8 + c0) * 17 + wid]           = pacc[0];
                gs[(r0 * 8 + c0 + 1) * 17 + wid]       = pacc[1];
                gs[((r0 + 8) * 8 + c0) * 17 + wid]     = pacc[2];
                gs[((r0 + 8) * 8 + c0 + 1) * 17 + wid] = pacc[3];
            }
            __syncthreads();

            // reduce 16 partials, write out + rounded h(t+1)
            if (tid < 128) {
                float v = 0.0f;
#pragma unroll
                for (int w = 0; w < 16; w++) v += gs[tid * 17 + w];
                int b = b0 + (tid >> 3);
                int p = p0 + (tid & 7);
                out[((size_t)b * NS + sd[d]) * (2 * NE) + d * NE + p] = v;
                g_hq[par ^ 1][d][b * NE + p] = cvt1(v);
            }
            __syncthreads();
            if (tid == 0) {
                __threadfence();
                strel(&g_flagH[d][bid * 16], (unsigned)(t + 1));
            }
        }
    }
}

// ----------------------------- launcher -------------------------------------
extern "C" void kernel_launch(void* const* d_in, const int* in_sizes, int n_in,
                              void* d_out, int out_size) {
    (void)in_sizes; (void)n_in; (void)out_size;
    const float* x    = (const float*)d_in[0];
    const float* Wihf = (const float*)d_in[1];
    const float* Whhf = (const float*)d_in[2];
    const float* bihf = (const float*)d_in[3];
    const float* bhhf = (const float*)d_in[4];
    const float* Whrf = (const float*)d_in[5];
    const float* Wihb = (const float*)d_in[6];
    const float* Whhb = (const float*)d_in[7];
    const float* bihb = (const float*)d_in[8];
    const float* bhhb = (const float*)d_in[9];
    const float* Whrb = (const float*)d_in[10];
    float* out = (float*)d_out;

    cudaFuncSetAttribute(lstm_kernel,
                         cudaFuncAttributeMaxDynamicSharedMemorySize,
                         POOL_FLOATS * 4);
    init_kernel<<<128, 512>>>();
    lstm_kernel<<<RBLK, 512, POOL_FLOATS * 4>>>(
        x, Wihf, Whhf, bihf, bhhf, Whrf,
        Wihb, Whhb, bihb, bhhb, Whrb, out);
}

// round 16
// speedup vs baseline: 1.2742x; 1.2742x over previous
#include <cuda_runtime.h>
#include <cstddef>
#include <cstdint>

// Sizes: B=64, S=1024, E=256 (== proj dim), H=1024, G=4*H=4096
#define NB 64
#define NS 1024
#define NE 256
#define NH 1024
#define NG 4096
#define RBLK 128     // 64 blocks per direction, 1/SM

// phase-2 smem pool (float offsets)
#define WHR_OFF 0                 // [16][1028] = 16448
#define HB_OFF 16448              // gates h: 2 halves x [64][132] = 16896
#define PART_OFF 16448            // proj partials [256][17] = 4352 (aliases HB)
#define AB_OFF 33344              // proj a: 16 warps x [16][68] = 17408
#define GS0_OFF 33344             // gates out kg0 [64][65] = 4160 (aliases AB)
#define GS1_OFF 37504             // gates out kg1 [64][65] = 4160
#define POOL_FLOATS 50752         // 203008 bytes
// phase-1 aliases (phase-separated by grid barrier)
#define P1_WS 0                   // 8*2304 = 18432
#define P1_AB 18432               // 4*2304 = 9216
#define P1_GS 27648               // 64*65  = 4160

// ---------------- device scratch (static: no runtime allocation) ------------
__device__ float g_xg[2][(size_t)NS * NB * NG];  // 2 GiB  xg [dir][s][b][g]
__device__ float g_xq[(size_t)NB * NS * NE];     // 64 MB  x rounded to tf32
__device__ float g_hq[2][2][NB * NE];            // [parity][dir] rounded h
__device__ float g_a[2][NB * NH];                // [dir][b*1024+j] rounded
__device__ unsigned g_ctr[4];
__device__ unsigned g_flagA[2][64 * 16];         // a(t) published (value t+1)
__device__ unsigned g_flagH[2][64 * 16];         // h(t+1) published (value t+1)

__device__ __forceinline__ float sigf(float x) { return 1.0f / (1.0f + __expf(-x)); }
__device__ __forceinline__ float tanh_f(float x) {
    float e = __expf(2.0f * x);
    return 1.0f - 2.0f / (e + 1.0f);
}

__device__ __forceinline__ uint4 cvt4(float4 v) {
    uint4 u;
    asm("cvt.rna.tf32.f32 %0, %1;" : "=r"(u.x) : "f"(v.x));
    asm("cvt.rna.tf32.f32 %0, %1;" : "=r"(u.y) : "f"(v.y));
    asm("cvt.rna.tf32.f32 %0, %1;" : "=r"(u.z) : "f"(v.z));
    asm("cvt.rna.tf32.f32 %0, %1;" : "=r"(u.w) : "f"(v.w));
    return u;
}
__device__ __forceinline__ float cvt1(float v) {
    uint32_t u;
    asm("cvt.rna.tf32.f32 %0, %1;" : "=r"(u) : "f"(v));
    return __uint_as_float(u);
}

__device__ __forceinline__ void mma_tf32(float* acc,
                                         uint32_t a0, uint32_t a1, uint32_t a2, uint32_t a3,
                                         uint32_t b0, uint32_t b1) {
    asm volatile(
        "mma.sync.aligned.m16n8k8.row.col.f32.tf32.tf32.f32 "
        "{%0,%1,%2,%3}, {%4,%5,%6,%7}, {%8,%9}, {%0,%1,%2,%3};"
        : "+f"(acc[0]), "+f"(acc[1]), "+f"(acc[2]), "+f"(acc[3])
        : "r"(a0), "r"(a1), "r"(a2), "r"(a3), "r"(b0), "r"(b1));
}

// phase-1 helper (stride-36 tiles)
template <int NTS>
__device__ __forceinline__ void warp_mma_chunk(const uint32_t* __restrict__ Au,
                                               const uint32_t* __restrict__ Bu,
                                               int mg, int ngb, int l,
                                               float acc[][4]) {
#pragma unroll
    for (int ks = 0; ks < 4; ks++) {
        int k0 = ks * 8 + (l & 3);
        int ra = (mg + (l >> 2)) * 36 + k0;
        uint32_t a0 = Au[ra];
        uint32_t a1 = Au[ra + 8 * 36];
        uint32_t a2 = Au[ra + 4];
        uint32_t a3 = Au[ra + 8 * 36 + 4];
#pragma unroll
        for (int nt = 0; nt < NTS; nt++) {
            int rb = (ngb + nt * 8 + (l >> 2)) * 36 + k0;
            mma_tf32(acc[nt], a0, a1, a2, a3, Bu[rb], Bu[rb + 4]);
        }
    }
}

__device__ __forceinline__ void fillA_raw(float* __restrict__ dst,
                                          const float* __restrict__ src,
                                          int k0, size_t rowstride, int t2) {
#pragma unroll
    for (int i = 0; i < 2; i++) {
        int f = t2 + i * 256;
        int r = f >> 3;
        int kq = (f & 7) << 2;
        float4 v = __ldcg((const float4*)&src[(size_t)r * rowstride + k0 + kq]);
        *(float4*)&dst[r * 36 + kq] = v;
    }
}

__device__ __forceinline__ unsigned ldacq(const unsigned* p) {
    unsigned v;
    asm volatile("ld.global.acquire.gpu.u32 %0, [%1];" : "=r"(v) : "l"(p) : "memory");
    return v;
}
__device__ __forceinline__ void strel(unsigned* p, unsigned v) {
    asm volatile("st.global.release.gpu.u32 [%0], %1;" :: "l"(p), "r"(v) : "memory");
}

__device__ __forceinline__ void cpa16(uint32_t saddr, const float* g) {
    asm volatile("cp.async.cg.shared.global [%0], [%1], 16;"
                 :: "r"(saddr), "l"(g) : "memory");
}
#define CP_COMMIT() asm volatile("cp.async.commit_group;" ::: "memory")
#define CP_WAIT0()  asm volatile("cp.async.wait_group 0;" ::: "memory")

__device__ __forceinline__ void gbar(unsigned* c, unsigned target) {
    __syncthreads();
    if (threadIdx.x == 0) {
        __threadfence();
        atomicAdd(c, 1u);
        unsigned v;
        do { v = ldacq(c); } while (v < target);
    }
    __syncthreads();
}

// --------------------------- init ------------------------------------------
__global__ void init_kernel() {
    int i = blockIdx.x * blockDim.x + threadIdx.x;   // 128 x 512 = 65536
    if (i < 4) g_ctr[i] = 0u;
    if (i < 2 * 64 * 16) {
        (&g_flagA[0][0])[i] = 0u;
        (&g_flagH[0][0])[i] = 0u;
    }
    if (i < 2 * 2 * NB * NE) (&g_hq[0][0][0])[i] = 0.0f;
}

// --------------------------- the whole network ------------------------------
__global__ __launch_bounds__(512, 1) void lstm_kernel(
    const float* __restrict__ x,
    const float* __restrict__ Wihf, const float* __restrict__ Whhf,
    const float* __restrict__ bihf, const float* __restrict__ bhhf,
    const float* __restrict__ Whrf,
    const float* __restrict__ Wihb, const float* __restrict__ Whhb,
    const float* __restrict__ bihb, const float* __restrict__ bhhb,
    const float* __restrict__ Whrb,
    float* __restrict__ out)
{
    extern __shared__ __align__(16) float pool[];

    const int bid = blockIdx.x;
    const int tid = threadIdx.x;
    const int l   = tid & 31;
    const int wid = tid >> 5;          // warp 0..15
    const int dir = bid >> 6;
    const int u   = bid & 63;

    // ---------------- phase 0: round x into g_xq ----------------------------
    {
        const size_t n4 = (size_t)NB * NS * NE / 4;
        for (size_t i4 = (size_t)bid * 512 + tid; i4 < n4; i4 += (size_t)RBLK * 512) {
            float4 v = ((const float4*)x)[i4];
            *(uint4*)&((float4*)g_xq)[i4] = cvt4(v);
        }
    }
    gbar(&g_ctr[0], (unsigned)RBLK);

    // ---------------- phase 1: xg = x @ W_ih^T + (b_ih + b_hh)  (R11) -------
    {
        const int kg = tid >> 8;
        const int t2 = tid & 255;
        const int wi = t2 >> 5;
        const int mg1 = (wi & 3) << 4;
        const int ngb = (wi >> 2) << 5;
        const int n0 = u << 6;
        const float* __restrict__ W  = dir ? Wihb : Wihf;
        const float* __restrict__ bi = dir ? bihb : bihf;
        const float* __restrict__ bh = dir ? bhhb : bhhf;
        float* __restrict__ xo = g_xg[dir];
        uint32_t* WS = (uint32_t*)(pool + P1_WS);
        float* Ab = pool + P1_AB + kg * 2 * 2304;
        float* gs1 = pool + P1_GS;

#pragma unroll
        for (int ci = 0; ci < 8; ci++) {
            int r = tid >> 3;
            int kq = (tid & 7) << 2;
            float4 wv = *(const float4*)&W[(size_t)(n0 + r) * NE + ci * 32 + kq];
            *(uint4*)&WS[ci * 2304 + r * 36 + kq] = cvt4(wv);
        }
        float bias0[4], bias1[4];
#pragma unroll
        for (int nt = 0; nt < 4; nt++) {
            int c = ngb + nt * 8 + ((l & 3) << 1);
            bias0[nt] = bi[n0 + c] + bh[n0 + c];
            bias1[nt] = bi[n0 + c + 1] + bh[n0 + c + 1];
        }
        __syncthreads();

        for (int s = 0; s < NS; s++) {
            const float* xsrc = g_xq + (size_t)s * NE;
            float acc[4][4];
#pragma unroll
            for (int a = 0; a < 4; a++)
#pragma unroll
                for (int q = 0; q < 4; q++) acc[a][q] = 0.0f;

            fillA_raw(Ab, xsrc, kg * 128, (size_t)NS * NE, t2);
            __syncthreads();
#pragma unroll
            for (int rr = 0; rr < 4; rr++) {
                if (rr < 3)
                    fillA_raw(Ab + ((rr + 1) & 1) * 2304, xsrc,
                              kg * 128 + (rr + 1) * 32, (size_t)NS * NE, t2);
                warp_mma_chunk<4>((uint32_t*)(Ab + (rr & 1) * 2304),
                                  WS + (kg * 4 + rr) * 2304, mg1, ngb, l, acc);
                __syncthreads();
            }
            if (kg == 1) {
#pragma unroll
                for (int nt = 0; nt < 4; nt++) {
                    int c = ngb + nt * 8 + ((l & 3) << 1);
                    int r = mg1 + (l >> 2);
                    gs1[c * 65 + r]           = acc[nt][0];
                    gs1[(c + 1) * 65 + r]     = acc[nt][1];
                    gs1[c * 65 + r + 8]       = acc[nt][2];
                    gs1[(c + 1) * 65 + r + 8] = acc[nt][3];
                }
            }
            __syncthreads();
            if (kg == 0) {
#pragma unroll
                for (int nt = 0; nt < 4; nt++) {
                    int c = ngb + nt * 8 + ((l & 3) << 1);
                    int r = mg1 + (l >> 2);
                    float2 o0, o1;
                    o0.x = acc[nt][0] + gs1[c * 65 + r] + bias0[nt];
                    o0.y = acc[nt][1] + gs1[(c + 1) * 65 + r] + bias1[nt];
                    o1.x = acc[nt][2] + gs1[c * 65 + r + 8] + bias0[nt];
                    o1.y = acc[nt][3] + gs1[(c + 1) * 65 + r + 8] + bias1[nt];
                    __stcs((float2*)&xo[((size_t)s * NB + r) * NG + n0 + c], o0);
                    __stcs((float2*)&xo[((size_t)s * NB + r + 8) * NG + n0 + c], o1);
                }
            }
            __syncthreads();
        }
    }
    gbar(&g_ctr[0], 2u * RBLK);

    // ---------------- phase 2: the recurrence -------------------------------
    const float* __restrict__ Whh = dir ? Whhb : Whhf;
    const float* __restrict__ Whr = dir ? Whrb : Whrf;
    const float* __restrict__ xg  = g_xg[dir];
    unsigned* flgA = &g_flagA[dir][0];
    unsigned* flgH = &g_flagH[dir][0];

    const int j0 = u << 4;                     // gates: 16 hidden units
    const int b0 = (u >> 4) << 4;              // proj: 16-batch tile
    const int p0 = (u & 15) << 4;              // proj: 16-col tile

    // gates warp tiling: m32 x n16 x k128  (2m x 4n x 2k = 16 warps)
    const int kgrp  = wid >> 3;                // K half
    const int wrem  = wid & 7;
    const int mgrp2 = (wrem & 1) << 5;         // 0 or 32
    const int ngrp  = (wrem >> 1) << 4;        // 0,16,32,48

    uint32_t* WhrS = (uint32_t*)(pool + WHR_OFF);
    const uint32_t sm_base = (uint32_t)__cvta_generic_to_shared(pool);

    // ---- Whr into smem once (tf32) ----------------------------------------
#pragma unroll
    for (int i = 0; i < 8; i++) {
        int f = tid + i * 512;                 // 0..4095
        int c = f >> 8;                        // 0..15
        int kq = (f & 255) << 2;               // 0..1020
        float4 wv = *(const float4*)&Whr[(size_t)(p0 + c) * NH + kq];
        *(uint4*)&WhrS[c * 1028 + kq] = cvt4(wv);
    }

    // ---- Whh fragments hoisted into registers ONCE -------------------------
    float bg0[16][2], bg1[16][2];
#pragma unroll
    for (int ks = 0; ks < 16; ks++) {
#pragma unroll
        for (int nt = 0; nt < 2; nt++) {
            int n = ngrp + nt * 8 + (l >> 2);
            int g = ((n >> 4) << 10) + j0 + (n & 15);
            int k = kgrp * 128 + ks * 8 + (l & 3);
            bg0[ks][nt] = cvt1(Whh[(size_t)g * NE + k]);
            bg1[ks][nt] = cvt1(Whh[(size_t)g * NE + k + 4]);
        }
    }
    __syncthreads();

    float creg[2] = {0.0f, 0.0f};              // cell state in registers
    const int jl = tid & 15;                   // cell mapping helpers

    for (int t = 0; t < NS; t++) {
        const int par = t & 1;
        const int s_eff = dir ? (NS - 1 - t) : t;

        // xg prefetch (issued before the h wait; covers DRAM latency)
        float xgi[2], xgf[2], xgg[2], xgo[2];
#pragma unroll
        for (int i = 0; i < 2; i++) {
            int m = tid + i * 512;
            int jj = m & 15, b = m >> 4;
            const float* p = &xg[((size_t)s_eff * NB + b) * NG + j0 + jj];
            xgi[i] = __ldcs(p);
            xgf[i] = __ldcs(p + 1024);
            xgg[i] = __ldcs(p + 2048);
            xgo[i] = __ldcs(p + 3072);
        }

        // ---- wait h(t) published by all 64 blocks -------------------------
        if (t > 0) {
            if (tid < 64) {
                while (ldacq(&flgH[tid * 16]) < (unsigned)t) { }
            }
        }
        __syncthreads();

        // ---- gates: fill own K-half of h via cp.async, half-barrier -------
        {
            const float* hsrc = g_hq[par][dir];
            uint32_t hb_s = sm_base + (HB_OFF + kgrp * 8448) * 4;
            int wh = wid & 7;
#pragma unroll
            for (int i = 0; i < 8; i++) {
                int idx = wh * 256 + i * 32 + l;       // 0..2047
                int r = idx >> 5;
                int c4 = (idx & 31) << 2;
                cpa16(hb_s + (unsigned)(r * 132 + c4) * 4,
                      &hsrc[r * NE + kgrp * 128 + c4]);
            }
            CP_COMMIT();
            CP_WAIT0();
            asm volatile("bar.sync %0, %1;" :: "r"(kgrp + 1), "r"(256) : "memory");
        }

        // ---- gates MMA: K=128 per warp, B from registers ------------------
        {
            const uint32_t* hb = (const uint32_t*)(pool + HB_OFF + kgrp * 8448);
            float acc[2][2][4];
#pragma unroll
            for (int mt = 0; mt < 2; mt++)
#pragma unroll
                for (int nt = 0; nt < 2; nt++)
#pragma unroll
                    for (int q = 0; q < 4; q++) acc[mt][nt][q] = 0.0f;

#pragma unroll
            for (int ks = 0; ks < 16; ks++) {
                int kb = ks * 8 + (l & 3);
#pragma unroll
                for (int mt = 0; mt < 2; mt++) {
                    int ra = (mgrp2 + mt * 16 + (l >> 2)) * 132 + kb;
                    uint32_t a0 = hb[ra];
                    uint32_t a1 = hb[ra + 8 * 132];
                    uint32_t a2 = hb[ra + 4];
                    uint32_t a3 = hb[ra + 8 * 132 + 4];
#pragma unroll
                    for (int nt = 0; nt < 2; nt++)
                        mma_tf32(acc[mt][nt], a0, a1, a2, a3,
                                 __float_as_uint(bg0[ks][nt]),
                                 __float_as_uint(bg1[ks][nt]));
                }
            }
            // write per-half gate sums to gs0/gs1 (no inter-half sync needed)
            float* gsK = pool + GS0_OFF + kgrp * 4160;
#pragma unroll
            for (int mt = 0; mt < 2; mt++) {
#pragma unroll
                for (int nt = 0; nt < 2; nt++) {
                    int c = ngrp + nt * 8 + ((l & 3) << 1);
                    int r = mgrp2 + mt * 16 + (l >> 2);
                    gsK[c * 65 + r]           = acc[mt][nt][0];
                    gsK[(c + 1) * 65 + r]     = acc[mt][nt][1];
                    gsK[c * 65 + r + 8]       = acc[mt][nt][2];
                    gsK[(c + 1) * 65 + r + 8] = acc[mt][nt][3];
                }
            }
            __syncthreads();
        }

        // ---- cell update (sum both K-halves), rounded a to global ---------
        {
            const float* gs0 = pool + GS0_OFF;
            const float* gs1 = pool + GS1_OFF;
#pragma unroll
            for (int i = 0; i < 2; i++) {
                int m = tid + i * 512;
                int jj = m & 15, b = m >> 4;
                float gi = gs0[( 0 + jj) * 65 + b] + gs1[( 0 + jj) * 65 + b] + xgi[i];
                float gf = gs0[(16 + jj) * 65 + b] + gs1[(16 + jj) * 65 + b] + xgf[i];
                float gg = gs0[(32 + jj) * 65 + b] + gs1[(32 + jj) * 65 + b] + xgg[i];
                float go = gs0[(48 + jj) * 65 + b] + gs1[(48 + jj) * 65 + b] + xgo[i];
                float cn = sigf(gf) * creg[i] + sigf(gi) * tanh_f(gg);
                creg[i] = cn;
                g_a[dir][b * NH + j0 + jj] = cvt1(sigf(go) * tanh_f(cn));
            }
            __syncthreads();
            if (tid == 0) {
                __threadfence();
                strel(&flgA[u * 16], (unsigned)(t + 1));
            }
        }

        // ---- projection (dataflow): each warp waits only its 4 producers --
        {
            if (l < 4) {
                while (ldacq(&flgA[(wid * 4 + l) * 16]) < (unsigned)(t + 1)) { }
            }
            __syncwarp();

            // fill own K-slice: rows b0..b0+15, cols [wid*64, wid*64+64)
            uint32_t ab_s = sm_base + (AB_OFF + wid * 1088) * 4;
#pragma unroll
            for (int i = 0; i < 8; i++) {
                int idx = i * 32 + l;                  // 0..255
                int r = idx >> 4;
                int c4 = (idx & 15) << 2;
                cpa16(ab_s + (unsigned)(r * 68 + c4) * 4,
                      &g_a[dir][(size_t)(b0 + r) * NH + wid * 64 + c4]);
            }
            CP_COMMIT();
            CP_WAIT0();
            __syncwarp();

            const uint32_t* aU = (const uint32_t*)(pool + AB_OFF + wid * 1088);
            float pacc[2][4];
#pragma unroll
            for (int nt = 0; nt < 2; nt++)
#pragma unroll
                for (int q = 0; q < 4; q++) pacc[nt][q] = 0.0f;

#pragma unroll
            for (int ks = 0; ks < 8; ks++) {
                int kb = ks * 8 + (l & 3);
                int ra = (l >> 2) * 68 + kb;
                uint32_t a0 = aU[ra];
                uint32_t a1 = aU[ra + 8 * 68];
                uint32_t a2 = aU[ra + 4];
                uint32_t a3 = aU[ra + 8 * 68 + 4];
                int kglob = wid * 64 + kb;
#pragma unroll
                for (int nt = 0; nt < 2; nt++) {
                    int rb = (nt * 8 + (l >> 2)) * 1028 + kglob;
                    mma_tf32(pacc[nt], a0, a1, a2, a3, WhrS[rb], WhrS[rb + 4]);
                }
            }
            // partials -> PART[(r*16+c)*17 + wid]
            float* pp = pool + PART_OFF;
#pragma unroll
            for (int nt = 0; nt < 2; nt++) {
                int c0 = nt * 8 + ((l & 3) << 1);
                int r0 = l >> 2;
                pp[(r0 * 16 + c0) * 17 + wid]           = pacc[nt][0];
                pp[(r0 * 16 + c0 + 1) * 17 + wid]       = pacc[nt][1];
                pp[((r0 + 8) * 16 + c0) * 17 + wid]     = pacc[nt][2];
                pp[((r0 + 8) * 16 + c0 + 1) * 17 + wid] = pacc[nt][3];
            }
            __syncthreads();

            // reduce 16 partials, write out + rounded h(t+1)
            if (tid < 256) {
                const float* ppr = pool + PART_OFF;
                float v = 0.0f;
#pragma unroll
                for (int w = 0; w < 16; w++) v += ppr[tid * 17 + w];
                int b = b0 + (tid >> 4);
                int p = p0 + (tid & 15);
                out[((size_t)b * NS + s_eff) * (2 * NE) + dir * NE + p] = v;
                g_hq[par ^ 1][dir][b * NE + p] = cvt1(v);
            }
            __syncthreads();
            if (tid == 0) {
                __threadfence();
                strel(&flgH[u * 16], (unsigned)(t + 1));
            }
        }
    }
    (void)jl;
}

// ----------------------------- launcher -------------------------------------
extern "C" void kernel_launch(void* const* d_in, const int* in_sizes, int n_in,
                              void* d_out, int out_size) {
    (void)in_sizes; (void)n_in; (void)out_size;
    const float* x    = (const float*)d_in[0];
    const float* Wihf = (const float*)d_in[1];
    const float* Whhf = (const float*)d_in[2];
    const float* bihf = (const float*)d_in[3];
    const float* bhhf = (const float*)d_in[4];
    const float* Whrf = (const float*)d_in[5];
    const float* Wihb = (const float*)d_in[6];
    const float* Whhb = (const float*)d_in[7];
    const float* bihb = (const float*)d_in[8];
    const float* bhhb = (const float*)d_in[9];
    const float* Whrb = (const float*)d_in[10];
    float* out = (float*)d_out;

    cudaFuncSetAttribute(lstm_kernel,
                         cudaFuncAttributeMaxDynamicSharedMemorySize,
                         POOL_FLOATS * 4);
    init_kernel<<<128, 512>>>();
    lstm_kernel<<<RBLK, 512, POOL_FLOATS * 4>>>(
        x, Wihf, Whhf, bihf, bhhf, Whrf,
        Wihb, Whhb, bihb, bhhb, Whrb, out);
}